// round 16
// baseline (speedup 1.0000x reference)
#include <cuda_runtime.h>
#include <cuda_bf16.h>
#include <cstdint>

#define HH 128
#define WW 128
#define HWSZ (128*128)
#define CIN 64
#define COUT 64
#define BATCH 8

// scratch (__device__ globals: allocation-free)
__device__ float g_off[BATCH * 27 * HWSZ];   // [b][27][H][W]
__device__ float4 g_x4[(size_t)BATCH * 16 * HWSZ];  // c4-packed NCHW x (33.5 MB)
// B weight fragments for mma.sync m16n8k16 (k-permuted: ch = 4q+2bb+w):
// deform: step s = cc*9 + kk (cc-outer);  u32 index = ((s*8 + j)*32 + lane)*2 + bb
__device__ uint32_t g_wfh[36 * 8 * 32 * 2];
__device__ uint32_t g_wfl[36 * 8 * 32 * 2];
// conv_om weight fragments (N=32: 27 outputs zero-padded), step s = kk*4+cc (kk-outer)
__device__ uint32_t g_cfh[36 * 4 * 32 * 2];
__device__ uint32_t g_cfl[36 * 4 * 32 * 2];

static __device__ __forceinline__ uint32_t bf16pk(float a, float b) {
    __nv_bfloat16 ha = __float2bfloat16(a);
    __nv_bfloat16 hb = __float2bfloat16(b);
    return (uint32_t)__bfloat16_as_ushort(ha)
         | ((uint32_t)__bfloat16_as_ushort(hb) << 16);
}

// ---- pack: x NCHW -> g_x4 (channel-quad interleave, position-major kept) ----
__global__ __launch_bounds__(256) void pack_kernel(const float* __restrict__ x) {
    int idx = blockIdx.x * 256 + threadIdx.x;     // over BATCH*16*HWSZ
    int p = idx & (HWSZ - 1);
    int g = (idx >> 14) & 15;
    int b = idx >> 18;
    const float* src = x + ((size_t)b * 64 + g * 4) * HWSZ + p;
    g_x4[idx] = make_float4(src[0], src[HWSZ], src[2 * HWSZ], src[3 * HWSZ]);
}

// ---- prep: pack both weight sets into HMMA fragments (bf16 hi/lo split) ----
__global__ void prep_kernel(const float* __restrict__ weight,
                            const float* __restrict__ ow,
                            const float* __restrict__ mw) {
    int i = blockIdx.x * blockDim.x + threadIdx.x;
    if (i < 36 * 8 * 32 * 2) {
        int bb = i & 1;
        int lane = (i >> 1) & 31;
        int j = (i >> 6) & 7;
        int s = i >> 9;                 // 0..35  (deform: s = cc*9 + kk)
        int cc = s / 9;
        int kk = s - cc * 9;
        int kr = 4 * (lane & 3) + 2 * bb;   // permuted k
        int oc = j * 8 + (lane >> 2);
        int c0 = cc * 16 + kr;
        float w0 = weight[oc * 576 + c0 * 9 + kk];
        float w1 = weight[oc * 576 + (c0 + 1) * 9 + kk];
        __nv_bfloat16 h0 = __float2bfloat16(w0);
        __nv_bfloat16 h1 = __float2bfloat16(w1);
        g_wfh[i] = (uint32_t)__bfloat16_as_ushort(h0)
                 | ((uint32_t)__bfloat16_as_ushort(h1) << 16);
        g_wfl[i] = bf16pk(w0 - __bfloat162float(h0), w1 - __bfloat162float(h1));
    }
    if (i < 36 * 4 * 32 * 2) {
        int bb = i & 1;
        int lane = (i >> 1) & 31;
        int j = (i >> 6) & 3;
        int s = i >> 8;                 // 0..35  (conv_om: s = kk*4 + cc)
        int kk = s >> 2;
        int cc = s & 3;
        int kr = 4 * (lane & 3) + 2 * bb;   // permuted k
        int o = j * 8 + (lane >> 2);
        int c0 = cc * 16 + kr;
        float w0 = 0.f, w1 = 0.f;
        if (o < 18) {
            w0 = ow[o * 576 + c0 * 9 + kk];
            w1 = ow[o * 576 + (c0 + 1) * 9 + kk];
        } else if (o < 27) {
            w0 = mw[(o - 18) * 576 + c0 * 9 + kk];
            w1 = mw[(o - 18) * 576 + (c0 + 1) * 9 + kk];
        }
        __nv_bfloat16 h0 = __float2bfloat16(w0);
        __nv_bfloat16 h1 = __float2bfloat16(w1);
        g_cfh[i] = (uint32_t)__bfloat16_as_ushort(h0)
                 | ((uint32_t)__bfloat16_as_ushort(h1) << 16);
        g_cfl[i] = bf16pk(w0 - __bfloat162float(h0), w1 - __bfloat162float(h1));
    }
}

static __device__ __forceinline__ void mma_bf16(float* d, uint32_t a0, uint32_t a1,
                                                uint32_t a2, uint32_t a3,
                                                uint32_t b0, uint32_t b1) {
    asm volatile(
        "mma.sync.aligned.m16n8k16.row.col.f32.bf16.bf16.f32 "
        "{%0,%1,%2,%3}, {%4,%5,%6,%7}, {%8,%9}, {%0,%1,%2,%3};"
        : "+f"(d[0]), "+f"(d[1]), "+f"(d[2]), "+f"(d[3])
        : "r"(a0), "r"(a1), "r"(a2), "r"(a3), "r"(b0), "r"(b1));
}

// ---- kernel 1 (R14): offset+modulator conv, c4-packed loads ----
__global__ __launch_bounds__(256, 2) void conv_om_kernel(const float* __restrict__ ob,
                                                         const float* __restrict__ mb) {
    __shared__ __align__(16) unsigned short vSh[2][128][16];  // 8 KB
    __shared__ __align__(16) unsigned short vSl[2][128][16];  // 8 KB

    int t = threadIdx.x;
    int wid = t >> 5;
    int lid = t & 31;
    int ho = blockIdx.x;
    int b = blockIdx.y;
    const float4* x4b = g_x4 + (size_t)b * 16 * HWSZ;

    int sp = t & 127;
    int cl0 = (t >> 7) * 8;
    int g40 = cl0 >> 2;

    int pos0 = wid * 16;
    int r4 = lid >> 2;
    int q4 = lid & 3;

    float acc[4][4];
#pragma unroll
    for (int j = 0; j < 4; j++)
#pragma unroll
        for (int q = 0; q < 4; q++) acc[j][q] = 0.f;

    auto stage = [&](int it, int buf) {
        int kk = it >> 2;
        int cc = it & 3;
        int ki = kk / 3, kj = kk - ki * 3;
        int yo = ho - 1 + ki;
        int xo = sp - 1 + kj;
        bool valid = ((unsigned)yo < HH) && ((unsigned)xo < WW);
        float v[8];
        if (valid) {
            const float4* p4 = x4b + (size_t)(cc * 4 + g40) * HWSZ + yo * WW + xo;
            float4 u0 = __ldg(p4);
            float4 u1 = __ldg(p4 + HWSZ);
            v[0] = u0.x; v[1] = u0.y; v[2] = u0.z; v[3] = u0.w;
            v[4] = u1.x; v[5] = u1.y; v[6] = u1.z; v[7] = u1.w;
        } else {
#pragma unroll
            for (int i = 0; i < 8; i++) v[i] = 0.f;
        }
        uint32_t ph[4], pl[4];
#pragma unroll
        for (int j = 0; j < 4; j++) {
            __nv_bfloat16 h0 = __float2bfloat16(v[2 * j]);
            __nv_bfloat16 h1 = __float2bfloat16(v[2 * j + 1]);
            ph[j] = (uint32_t)__bfloat16_as_ushort(h0)
                  | ((uint32_t)__bfloat16_as_ushort(h1) << 16);
            pl[j] = bf16pk(v[2 * j] - __bfloat162float(h0),
                           v[2 * j + 1] - __bfloat162float(h1));
        }
        *(uint4*)&vSh[buf][sp][cl0] = make_uint4(ph[0], ph[1], ph[2], ph[3]);
        *(uint4*)&vSl[buf][sp][cl0] = make_uint4(pl[0], pl[1], pl[2], pl[3]);
    };

    stage(0, 0);

#pragma unroll 1
    for (int it = 0; it < 36; it++) {
        int buf = it & 1;

        __syncthreads();

        if (it + 1 < 36) stage(it + 1, buf ^ 1);

        {
            const char* bhp = (const char*)&vSh[buf][0][0];
            const char* blp = (const char*)&vSl[buf][0][0];
            uint32_t aoff = (uint32_t)((pos0 + r4) * 32 + q4 * 8);
            uint2 h0 = *(const uint2*)(bhp + aoff);
            uint2 h1 = *(const uint2*)(bhp + aoff + 256);
            uint2 l0 = *(const uint2*)(blp + aoff);
            uint2 l1 = *(const uint2*)(blp + aoff + 256);
#pragma unroll
            for (int j = 0; j < 4; j++) {
                uint2 bh2 = __ldg((const uint2*)&g_cfh[((it * 4 + j) * 32 + lid) * 2]);
                uint2 bl2 = __ldg((const uint2*)&g_cfl[((it * 4 + j) * 32 + lid) * 2]);
                mma_bf16(acc[j], h0.x, h1.x, h0.y, h1.y, bh2.x, bh2.y);
                mma_bf16(acc[j], h0.x, h1.x, h0.y, h1.y, bl2.x, bl2.y);
                mma_bf16(acc[j], l0.x, l1.x, l0.y, l1.y, bh2.x, bh2.y);
            }
        }
    }

    float* base = g_off + (size_t)b * 27 * HWSZ + ho * WW;
#pragma unroll
    for (int j = 0; j < 4; j++) {
        int oc0 = j * 8 + 2 * q4;
#pragma unroll
        for (int h = 0; h < 2; h++) {
            int o = oc0 + h;
            if (o < 27) {
                float v0 = acc[j][h];
                float v1 = acc[j][h + 2];
                if (o < 18) {
                    float bb = __ldg(ob + o);
                    v0 += bb; v1 += bb;
                } else {
                    float bb = __ldg(mb + o - 18);
                    v0 = 2.f / (1.f + __expf(-(v0 + bb)));
                    v1 = 2.f / (1.f + __expf(-(v1 + bb)));
                }
                base[(size_t)o * HWSZ + pos0 + r4] = v0;
                base[(size_t)o * HWSZ + pos0 + r4 + 8] = v1;
            }
        }
    }
}

// ---- bilinear tap metadata ----
struct Tap { float a00, a01, a10, a11; int o00, o01, o10, o11; };

static __device__ __forceinline__ Tap mk_tap(const float* __restrict__ offb,
                                             int pos, int ho, int xi,
                                             int ki, int kj) {
    Tap t;
    float dy = offb[(2 * ki * 3 + 2 * kj) * HWSZ + pos];
    float dx = offb[(2 * ki * 3 + 2 * kj + 1) * HWSZ + pos];
    float m  = offb[(18 + ki * 3 + kj) * HWSZ + pos];
    float fy = (float)(ho - 1 + ki) + dy;
    float fx = (float)(xi - 1 + kj) + dx;
    float fy0 = floorf(fy), fx0 = floorf(fx);
    int iy0 = (int)fy0, ix0 = (int)fx0;
    float wy = fy - fy0, wx = fx - fx0;
    bool vy0 = (unsigned)iy0 < HH;
    bool vy1 = (unsigned)(iy0 + 1) < HH;
    bool vx0 = (unsigned)ix0 < WW;
    bool vx1 = (unsigned)(ix0 + 1) < WW;
    t.a00 = (1.f - wy) * (1.f - wx) * m * ((vy0 && vx0) ? 1.f : 0.f);
    t.a01 = (1.f - wy) * wx         * m * ((vy0 && vx1) ? 1.f : 0.f);
    t.a10 = wy * (1.f - wx)         * m * ((vy1 && vx0) ? 1.f : 0.f);
    t.a11 = wy * wx                 * m * ((vy1 && vx1) ? 1.f : 0.f);
    int cy0 = min(max(iy0, 0), HH - 1);
    int cy1 = min(max(iy0 + 1, 0), HH - 1);
    int cx0 = min(max(ix0, 0), WW - 1);
    int cx1 = min(max(ix0 + 1, 0), WW - 1);
    t.o00 = cy0 * WW + cx0; t.o01 = cy0 * WW + cx1;
    t.o10 = cy1 * WW + cx0; t.o11 = cy1 * WW + cx1;
    return t;
}

// ---- kernel 2 v12: smem window gather (7x74 c4 window per cc) + HMMA ----
// Block = 64 positions. Dyn smem: window 33152 + tapw 9216 + tapo 2304 + vS 8192.
#define WIN_ROWS 7
#define WIN_COLS 74
#define WIN_PLANE (WIN_ROWS * WIN_COLS)          // 518
#define WIN_ELEMS (WIN_PLANE * 4)                // 2072 float4
#define OFF_TAPW 33152
#define OFF_TAPO 42368
#define OFF_VSH  44672
#define OFF_VSL  48768
#define DSMEM_TOT 52864

__global__ __launch_bounds__(256, 3) void deform_kernel(float* __restrict__ out) {
    extern __shared__ __align__(16) char smem[];
    float4* winS  = (float4*)smem;
    float4* tapwS = (float4*)(smem + OFF_TAPW);          // [kk*64+sp]
    int*    tapoS = (int*)(smem + OFF_TAPO);             // [kk*64+sp]
    unsigned short* vSh = (unsigned short*)(smem + OFF_VSH);  // [buf*1024 + sp*16 + c]
    unsigned short* vSl = (unsigned short*)(smem + OFF_VSL);

    int t = threadIdx.x;
    int wid = t >> 5;
    int lid = t & 31;
    int ho = blockIdx.x >> 1;
    int half = blockIdx.x & 1;
    int b = blockIdx.y;
    const float4* x4b = g_x4 + (size_t)b * 16 * HWSZ;
    const float* offb = g_off + (size_t)b * 27 * HWSZ;
    int wcol0 = half * 64;

    // staging mapping
    int sp = t & 63;
    int g4 = t >> 6;                   // c4 group 0..3
    int xi = wcol0 + sp;
    int spos = ho * WW + xi;

    // gemm mapping: warp = 16 pos x 32 oc
    int m = wid & 3;
    int j0 = (wid >> 2) * 4;
    int r4 = lid >> 2;
    int q4 = lid & 3;

    float acc[4][4];
#pragma unroll
    for (int j = 0; j < 4; j++)
#pragma unroll
        for (int q = 0; q < 4; q++) acc[j][q] = 0.f;

    // ---- build taps: 576 = 9 kk x 64 pos ----
#pragma unroll 1
    for (int idx = t; idx < 576; idx += 256) {
        int kk = idx >> 6;
        int sp2 = idx & 63;
        int ki = kk / 3, kj = kk - ki * 3;
        int xi2 = wcol0 + sp2;
        int pos2 = ho * WW + xi2;
        float dy = offb[(2 * kk) * HWSZ + pos2];
        float dx = offb[(2 * kk + 1) * HWSZ + pos2];
        float mm = offb[(18 + kk) * HWSZ + pos2];
        float fy = (float)(ho - 1 + ki) + dy;
        float fx = (float)(xi2 - 1 + kj) + dx;
        float fy0 = floorf(fy), fx0 = floorf(fx);
        int iy0 = (int)fy0, ix0 = (int)fx0;
        float wy = fy - fy0, wx = fx - fx0;
        bool vy0 = (unsigned)iy0 < HH;
        bool vy1 = (unsigned)(iy0 + 1) < HH;
        bool vx0 = (unsigned)ix0 < WW;
        bool vx1 = (unsigned)(ix0 + 1) < WW;
        float a00 = (1.f - wy) * (1.f - wx) * mm * ((vy0 && vx0) ? 1.f : 0.f);
        float a01 = (1.f - wy) * wx         * mm * ((vy0 && vx1) ? 1.f : 0.f);
        float a10 = wy * (1.f - wx)         * mm * ((vy1 && vx0) ? 1.f : 0.f);
        float a11 = wy * wx                 * mm * ((vy1 && vx1) ? 1.f : 0.f);
        tapwS[idx] = make_float4(a00, a01, a10, a11);
        int y0r = iy0 - (ho - 3);
        int x0w = ix0 - (wcol0 - 5);
        bool inw = ((unsigned)y0r <= 5u) && ((unsigned)x0w <= 72u);
        tapoS[idx] = inw ? (y0r * WIN_COLS + x0w) : -1;
    }

    auto load_window = [&](int cc) {
#pragma unroll 1
        for (int idx = t; idx < WIN_ELEMS; idx += 256) {
            int g = idx / WIN_PLANE;
            int rem = idx - g * WIN_PLANE;
            int r = rem / WIN_COLS;
            int ci = rem - r * WIN_COLS;
            int grow = min(max(ho - 3 + r, 0), HH - 1);
            int gcol = min(max(wcol0 - 5 + ci, 0), WW - 1);
            winS[idx] = __ldg(x4b + (size_t)(cc * 4 + g) * HWSZ + grow * WW + gcol);
        }
    };

    auto stage = [&](int cc, int kk, int buf) {
        int idx = kk * 64 + sp;
        float4 aw = tapwS[idx];
        int off = tapoS[idx];
        float4 cA, cB, cC, cD;
        if (off >= 0) {
            const float4* wg = winS + g4 * WIN_PLANE;
            cA = wg[off]; cB = wg[off + 1];
            cC = wg[off + WIN_COLS]; cD = wg[off + WIN_COLS + 1];
        } else {
            Tap g = mk_tap(offb, spos, ho, xi, kk / 3, kk % 3);
            const float4* p4 = x4b + (size_t)(cc * 4 + g4) * HWSZ;
            cA = __ldg(p4 + g.o00); cB = __ldg(p4 + g.o01);
            cC = __ldg(p4 + g.o10); cD = __ldg(p4 + g.o11);
        }
        float v0 = aw.x * cA.x + aw.y * cB.x + aw.z * cC.x + aw.w * cD.x;
        float v1 = aw.x * cA.y + aw.y * cB.y + aw.z * cC.y + aw.w * cD.y;
        float v2 = aw.x * cA.z + aw.y * cB.z + aw.z * cC.z + aw.w * cD.z;
        float v3 = aw.x * cA.w + aw.y * cB.w + aw.z * cC.w + aw.w * cD.w;
        __nv_bfloat16 h0 = __float2bfloat16(v0);
        __nv_bfloat16 h1 = __float2bfloat16(v1);
        __nv_bfloat16 h2 = __float2bfloat16(v2);
        __nv_bfloat16 h3 = __float2bfloat16(v3);
        uint32_t ph0 = (uint32_t)__bfloat16_as_ushort(h0)
                     | ((uint32_t)__bfloat16_as_ushort(h1) << 16);
        uint32_t ph1 = (uint32_t)__bfloat16_as_ushort(h2)
                     | ((uint32_t)__bfloat16_as_ushort(h3) << 16);
        uint32_t pl0 = bf16pk(v0 - __bfloat162float(h0), v1 - __bfloat162float(h1));
        uint32_t pl1 = bf16pk(v2 - __bfloat162float(h2), v3 - __bfloat162float(h3));
        *(uint2*)&vSh[buf * 1024 + sp * 16 + g4 * 4] = make_uint2(ph0, ph1);
        *(uint2*)&vSl[buf * 1024 + sp * 16 + g4 * 4] = make_uint2(pl0, pl1);
    };

#pragma unroll 1
    for (int cc = 0; cc < 4; cc++) {
        __syncthreads();        // taps ready (cc=0) / prior window reads done
        load_window(cc);
        __syncthreads();        // window visible
        stage(cc, 0, (cc * 9) & 1);

#pragma unroll 1
        for (int kk = 0; kk < 9; kk++) {
            int it = cc * 9 + kk;
            int buf = it & 1;

            __syncthreads();    // vS[buf] visible

            if (kk < 9 - 1) stage(cc, kk + 1, buf ^ 1);

            {
                const char* bhp = (const char*)(vSh + buf * 1024);
                const char* blp = (const char*)(vSl + buf * 1024);
                uint32_t aoff = (uint32_t)((m * 16 + r4) * 32 + q4 * 8);
                uint2 h0 = *(const uint2*)(bhp + aoff);
                uint2 h1 = *(const uint2*)(bhp + aoff + 256);
                uint2 l0 = *(const uint2*)(blp + aoff);
                uint2 l1 = *(const uint2*)(blp + aoff + 256);
#pragma unroll
                for (int jj = 0; jj < 4; jj++) {
                    int j = j0 + jj;
                    uint2 bh2 = __ldg((const uint2*)&g_wfh[((it * 8 + j) * 32 + lid) * 2]);
                    uint2 bl2 = __ldg((const uint2*)&g_wfl[((it * 8 + j) * 32 + lid) * 2]);
                    mma_bf16(acc[jj], h0.x, h1.x, h0.y, h1.y, bh2.x, bh2.y);
                    mma_bf16(acc[jj], h0.x, h1.x, h0.y, h1.y, bl2.x, bl2.y);
                    mma_bf16(acc[jj], l0.x, l1.x, l0.y, l1.y, bh2.x, bh2.y);
                }
            }
        }
    }

    float* ob = out + (size_t)b * COUT * HWSZ + ho * WW + half * 64;
#pragma unroll
    for (int jj = 0; jj < 4; jj++) {
        int oc = (j0 + jj) * 8 + q4 * 2;
        int p = m * 16 + r4;
        ob[(size_t)oc * HWSZ + p]           = acc[jj][0];
        ob[(size_t)(oc + 1) * HWSZ + p]     = acc[jj][1];
        ob[(size_t)oc * HWSZ + p + 8]       = acc[jj][2];
        ob[(size_t)(oc + 1) * HWSZ + p + 8] = acc[jj][3];
    }
}

extern "C" void kernel_launch(void* const* d_in, const int* in_sizes, int n_in,
                              void* d_out, int out_size) {
    const float* x  = (const float*)d_in[0];  // [8,64,128,128]
    const float* ow = (const float*)d_in[1];  // [18,64,3,3]
    const float* ob = (const float*)d_in[2];  // [18]
    const float* mw = (const float*)d_in[3];  // [9,64,3,3]
    const float* mb = (const float*)d_in[4];  // [9]
    const float* wt = (const float*)d_in[5];  // [64,64,3,3]
    float* out = (float*)d_out;               // [8,64,128,128]

    // idempotent, deterministic, not a stream op (capture-safe)
    cudaFuncSetAttribute(deform_kernel,
                         cudaFuncAttributeMaxDynamicSharedMemorySize, DSMEM_TOT);

    prep_kernel<<<72, 256>>>(wt, ow, mw);

    pack_kernel<<<(BATCH * 16 * HWSZ) / 256, 256>>>(x);

    dim3 g1(HH, BATCH);
    conv_om_kernel<<<g1, 256>>>(ob, mb);

    dim3 g2(HH * 2, BATCH);
    deform_kernel<<<g2, 256, DSMEM_TOT>>>(out);
}

// round 17
// speedup vs baseline: 1.5111x; 1.5111x over previous
#include <cuda_runtime.h>
#include <cuda_fp16.h>
#include <cstdint>

#define HH 128
#define WW 128
#define HWSZ (128*128)
#define CIN 64
#define COUT 64
#define BATCH 8

// scratch (__device__ globals: allocation-free)
__device__ float g_off[BATCH * 27 * HWSZ];   // [b][27][H][W]
__device__ float4 g_x4[(size_t)BATCH * 16 * HWSZ];  // c4-packed NCHW x (33.5 MB)
// B weight fragments for mma.sync m16n8k16 fp16 (k-permuted: ch = 4q+2bb+w):
// u32 index = ((s*8 + j)*32 + lane)*2 + bb ; s = kk*4+cc, j = n8 block(8)
__device__ uint32_t g_wf[36 * 8 * 32 * 2];
// conv_om weight fragments (N=32: 27 outputs zero-padded), 4 n8 blocks
__device__ uint32_t g_cf[36 * 4 * 32 * 2];

static __device__ __forceinline__ uint32_t f16pk(float a, float b) {
    __half2 h = __floats2half2_rn(a, b);
    return *(uint32_t*)&h;
}

// ---- pack: x NCHW -> g_x4 (channel-quad interleave, position-major kept) ----
__global__ __launch_bounds__(256) void pack_kernel(const float* __restrict__ x) {
    int idx = blockIdx.x * 256 + threadIdx.x;     // over BATCH*16*HWSZ
    int p = idx & (HWSZ - 1);
    int g = (idx >> 14) & 15;
    int b = idx >> 18;
    const float* src = x + ((size_t)b * 64 + g * 4) * HWSZ + p;
    g_x4[idx] = make_float4(src[0], src[HWSZ], src[2 * HWSZ], src[3 * HWSZ]);
}

// ---- prep: pack both weight sets into fp16 HMMA fragments ----
// k-permutation: fragment slot (q = lane&3, bb = k-half, w) holds channel 4q+2bb+w
__global__ void prep_kernel(const float* __restrict__ weight,
                            const float* __restrict__ ow,
                            const float* __restrict__ mw) {
    int i = blockIdx.x * blockDim.x + threadIdx.x;
    if (i < 36 * 8 * 32 * 2) {
        int bb = i & 1;
        int lane = (i >> 1) & 31;
        int j = (i >> 6) & 7;
        int s = i >> 9;                 // 0..35
        int kk = s >> 2;
        int cc = s & 3;
        int kr = 4 * (lane & 3) + 2 * bb;   // permuted k
        int oc = j * 8 + (lane >> 2);
        int c0 = cc * 16 + kr;
        float w0 = weight[oc * 576 + c0 * 9 + kk];
        float w1 = weight[oc * 576 + (c0 + 1) * 9 + kk];
        g_wf[i] = f16pk(w0, w1);
    }
    if (i < 36 * 4 * 32 * 2) {
        int bb = i & 1;
        int lane = (i >> 1) & 31;
        int j = (i >> 6) & 3;
        int s = i >> 8;                 // 0..35
        int kk = s >> 2;
        int cc = s & 3;
        int kr = 4 * (lane & 3) + 2 * bb;   // permuted k
        int o = j * 8 + (lane >> 2);
        int c0 = cc * 16 + kr;
        float w0 = 0.f, w1 = 0.f;
        if (o < 18) {
            w0 = ow[o * 576 + c0 * 9 + kk];
            w1 = ow[o * 576 + (c0 + 1) * 9 + kk];
        } else if (o < 27) {
            w0 = mw[(o - 18) * 576 + c0 * 9 + kk];
            w1 = mw[(o - 18) * 576 + (c0 + 1) * 9 + kk];
        }
        g_cf[i] = f16pk(w0, w1);
    }
}

static __device__ __forceinline__ void mma_f16(float* d, uint32_t a0, uint32_t a1,
                                               uint32_t a2, uint32_t a3,
                                               uint32_t b0, uint32_t b1) {
    asm volatile(
        "mma.sync.aligned.m16n8k16.row.col.f32.f16.f16.f32 "
        "{%0,%1,%2,%3}, {%4,%5,%6,%7}, {%8,%9}, {%0,%1,%2,%3};"
        : "+f"(d[0]), "+f"(d[1]), "+f"(d[2]), "+f"(d[3])
        : "r"(a0), "r"(a1), "r"(a2), "r"(a3), "r"(b0), "r"(b1));
}

// ---- kernel 1: offset+modulator conv, c4-packed loads, fp16 single-plane ----
__global__ __launch_bounds__(256, 3) void conv_om_kernel(const float* __restrict__ ob,
                                                         const float* __restrict__ mb) {
    __shared__ __align__(16) unsigned short vS[2][128][16];   // 8 KB

    int t = threadIdx.x;
    int wid = t >> 5;
    int lid = t & 31;
    int ho = blockIdx.x;
    int b = blockIdx.y;
    const float4* x4b = g_x4 + (size_t)b * 16 * HWSZ;

    int sp = t & 127;
    int cl0 = (t >> 7) * 8;
    int g40 = cl0 >> 2;                  // 0 or 2: first c4-group within chunk

    int pos0 = wid * 16;
    int r4 = lid >> 2;
    int q4 = lid & 3;

    float acc[4][4];
#pragma unroll
    for (int j = 0; j < 4; j++)
#pragma unroll
        for (int q = 0; q < 4; q++) acc[j][q] = 0.f;

    auto stage = [&](int it, int buf) {
        int kk = it >> 2;
        int cc = it & 3;
        int ki = kk / 3, kj = kk - ki * 3;
        int yo = ho - 1 + ki;
        int xo = sp - 1 + kj;
        bool valid = ((unsigned)yo < HH) && ((unsigned)xo < WW);
        float v[8];
        if (valid) {
            const float4* p4 = x4b + (size_t)(cc * 4 + g40) * HWSZ + yo * WW + xo;
            float4 u0 = __ldg(p4);
            float4 u1 = __ldg(p4 + HWSZ);
            v[0] = u0.x; v[1] = u0.y; v[2] = u0.z; v[3] = u0.w;
            v[4] = u1.x; v[5] = u1.y; v[6] = u1.z; v[7] = u1.w;
        } else {
#pragma unroll
            for (int i = 0; i < 8; i++) v[i] = 0.f;
        }
        uint32_t ph[4];
#pragma unroll
        for (int j = 0; j < 4; j++)
            ph[j] = f16pk(v[2 * j], v[2 * j + 1]);
        *(uint4*)&vS[buf][sp][cl0] = make_uint4(ph[0], ph[1], ph[2], ph[3]);
    };

    stage(0, 0);

#pragma unroll 1
    for (int it = 0; it < 36; it++) {
        int buf = it & 1;

        __syncthreads();

        if (it + 1 < 36) stage(it + 1, buf ^ 1);

        {
            const char* bp = (const char*)&vS[buf][0][0];
            uint32_t aoff = (uint32_t)((pos0 + r4) * 32 + q4 * 8);
            uint2 a02 = *(const uint2*)(bp + aoff);          // (a0, a2)
            uint2 a13 = *(const uint2*)(bp + aoff + 256);    // (a1, a3)
#pragma unroll
            for (int j = 0; j < 4; j++) {
                uint2 b2 = __ldg((const uint2*)&g_cf[((it * 4 + j) * 32 + lid) * 2]);
                mma_f16(acc[j], a02.x, a13.x, a02.y, a13.y, b2.x, b2.y);
            }
        }
    }

    float* base = g_off + (size_t)b * 27 * HWSZ + ho * WW;
#pragma unroll
    for (int j = 0; j < 4; j++) {
        int oc0 = j * 8 + 2 * q4;
#pragma unroll
        for (int h = 0; h < 2; h++) {
            int o = oc0 + h;
            if (o < 27) {
                float v0 = acc[j][h];
                float v1 = acc[j][h + 2];
                if (o < 18) {
                    float bb = __ldg(ob + o);
                    v0 += bb; v1 += bb;
                } else {
                    float bb = __ldg(mb + o - 18);
                    v0 = 2.f / (1.f + __expf(-(v0 + bb)));
                    v1 = 2.f / (1.f + __expf(-(v1 + bb)));
                }
                base[(size_t)o * HWSZ + pos0 + r4] = v0;
                base[(size_t)o * HWSZ + pos0 + r4 + 8] = v1;
            }
        }
    }
}

// ---- bilinear tap metadata ----
struct Tap { float a00, a01, a10, a11; int o00, o01, o10, o11; };

static __device__ __forceinline__ Tap mk_tap(const float* __restrict__ offb,
                                             int pos, int ho, int xi,
                                             int ki, int kj) {
    Tap t;
    float dy = offb[(2 * ki * 3 + 2 * kj) * HWSZ + pos];
    float dx = offb[(2 * ki * 3 + 2 * kj + 1) * HWSZ + pos];
    float m  = offb[(18 + ki * 3 + kj) * HWSZ + pos];
    float fy = (float)(ho - 1 + ki) + dy;
    float fx = (float)(xi - 1 + kj) + dx;
    float fy0 = floorf(fy), fx0 = floorf(fx);
    int iy0 = (int)fy0, ix0 = (int)fx0;
    float wy = fy - fy0, wx = fx - fx0;
    bool vy0 = (unsigned)iy0 < HH;
    bool vy1 = (unsigned)(iy0 + 1) < HH;
    bool vx0 = (unsigned)ix0 < WW;
    bool vx1 = (unsigned)(ix0 + 1) < WW;
    t.a00 = (1.f - wy) * (1.f - wx) * m * ((vy0 && vx0) ? 1.f : 0.f);
    t.a01 = (1.f - wy) * wx         * m * ((vy0 && vx1) ? 1.f : 0.f);
    t.a10 = wy * (1.f - wx)         * m * ((vy1 && vx0) ? 1.f : 0.f);
    t.a11 = wy * wx                 * m * ((vy1 && vx1) ? 1.f : 0.f);
    int cy0 = min(max(iy0, 0), HH - 1);
    int cy1 = min(max(iy0 + 1, 0), HH - 1);
    int cx0 = min(max(ix0, 0), WW - 1);
    int cx1 = min(max(ix0 + 1, 0), WW - 1);
    t.o00 = cy0 * WW + cx0; t.o01 = cy0 * WW + cx1;
    t.o10 = cy1 * WW + cx0; t.o11 = cy1 * WW + cx1;
    return t;
}

// ---- kernel 2: c4 LDG.128 gather + fp16 single-plane HMMA (R14 structure) ----
__global__ __launch_bounds__(256, 3) void deform_kernel(float* __restrict__ out) {
    __shared__ __align__(16) unsigned short vS[2][128][16];   // 8 KB

    int t = threadIdx.x;
    int wid = t >> 5;
    int lid = t & 31;
    int ho = blockIdx.x;
    int b = blockIdx.y;
    const float4* x4b = g_x4 + (size_t)b * 16 * HWSZ;
    const float* offb = g_off + (size_t)b * 27 * HWSZ;

    int sp = t & 127;
    int cl0 = (t >> 7) * 8;
    int g40 = cl0 >> 2;                  // 0 or 2
    int spos = ho * WW + sp;

    // gemm mapping: warp = 32 pos (2 m16 tiles) x 32 oc (4 j blocks)
    int pos0 = (wid & 3) * 32;
    int j0 = (wid >> 2) * 4;
    int r4 = lid >> 2;
    int q4 = lid & 3;

    float acc[2][4][4];
#pragma unroll
    for (int mt = 0; mt < 2; mt++)
#pragma unroll
        for (int j = 0; j < 4; j++)
#pragma unroll
            for (int q = 0; q < 4; q++) acc[mt][j][q] = 0.f;

    Tap tp = mk_tap(offb, spos, ho, sp, 0, 0);

    auto stage = [&](const Tap& g, int cc, int buf) {
        const float4* xc4 = x4b + (size_t)(cc * 4 + g40) * HWSZ;
        float v[8];
#pragma unroll
        for (int gq = 0; gq < 2; gq++) {
            const float4* p4 = xc4 + (size_t)gq * HWSZ;
            float4 cA = __ldg(p4 + g.o00);
            float4 cB = __ldg(p4 + g.o01);
            float4 cC = __ldg(p4 + g.o10);
            float4 cD = __ldg(p4 + g.o11);
            v[gq * 4 + 0] = g.a00 * cA.x + g.a01 * cB.x + g.a10 * cC.x + g.a11 * cD.x;
            v[gq * 4 + 1] = g.a00 * cA.y + g.a01 * cB.y + g.a10 * cC.y + g.a11 * cD.y;
            v[gq * 4 + 2] = g.a00 * cA.z + g.a01 * cB.z + g.a10 * cC.z + g.a11 * cD.z;
            v[gq * 4 + 3] = g.a00 * cA.w + g.a01 * cB.w + g.a10 * cC.w + g.a11 * cD.w;
        }
        uint32_t ph[4];
#pragma unroll
        for (int j = 0; j < 4; j++)
            ph[j] = f16pk(v[2 * j], v[2 * j + 1]);
        *(uint4*)&vS[buf][sp][cl0] = make_uint4(ph[0], ph[1], ph[2], ph[3]);
    };

    stage(tp, 0, 0);

#pragma unroll 1
    for (int it = 0; it < 36; it++) {
        int buf = it & 1;

        __syncthreads();

        if (it + 1 < 36) {
            int itn = it + 1;
            int kkn = itn >> 2;
            int ccn = itn & 3;
            if (ccn == 0) tp = mk_tap(offb, spos, ho, sp, kkn / 3, kkn % 3);
            stage(tp, ccn, itn & 1);
        }

        {
            const char* bp = (const char*)&vS[buf][0][0];
            uint2 a02[2], a13[2];
#pragma unroll
            for (int mt = 0; mt < 2; mt++) {
                uint32_t aoff = (uint32_t)((pos0 + mt * 16 + r4) * 32 + q4 * 8);
                a02[mt] = *(const uint2*)(bp + aoff);          // (a0, a2)
                a13[mt] = *(const uint2*)(bp + aoff + 256);    // (a1, a3)
            }
#pragma unroll
            for (int jj = 0; jj < 4; jj++) {
                int j = j0 + jj;
                uint2 b2 = __ldg((const uint2*)&g_wf[((it * 8 + j) * 32 + lid) * 2]);
#pragma unroll
                for (int mt = 0; mt < 2; mt++)
                    mma_f16(acc[mt][jj], a02[mt].x, a13[mt].x, a02[mt].y, a13[mt].y,
                            b2.x, b2.y);
            }
        }
    }

    float* ob = out + (size_t)b * COUT * HWSZ + ho * WW;
#pragma unroll
    for (int mt = 0; mt < 2; mt++) {
#pragma unroll
        for (int jj = 0; jj < 4; jj++) {
            int oc = (j0 + jj) * 8 + q4 * 2;
            int p = pos0 + mt * 16 + r4;
            ob[(size_t)oc * HWSZ + p]           = acc[mt][jj][0];
            ob[(size_t)(oc + 1) * HWSZ + p]     = acc[mt][jj][1];
            ob[(size_t)oc * HWSZ + p + 8]       = acc[mt][jj][2];
            ob[(size_t)(oc + 1) * HWSZ + p + 8] = acc[mt][jj][3];
        }
    }
}

extern "C" void kernel_launch(void* const* d_in, const int* in_sizes, int n_in,
                              void* d_out, int out_size) {
    const float* x  = (const float*)d_in[0];  // [8,64,128,128]
    const float* ow = (const float*)d_in[1];  // [18,64,3,3]
    const float* ob = (const float*)d_in[2];  // [18]
    const float* mw = (const float*)d_in[3];  // [9,64,3,3]
    const float* mb = (const float*)d_in[4];  // [9]
    const float* wt = (const float*)d_in[5];  // [64,64,3,3]
    float* out = (float*)d_out;               // [8,64,128,128]

    prep_kernel<<<72, 256>>>(wt, ow, mw);

    pack_kernel<<<(BATCH * 16 * HWSZ) / 256, 256>>>(x);

    dim3 g1(HH, BATCH);
    conv_om_kernel<<<g1, 256>>>(ob, mb);

    dim3 g2(HH, BATCH);
    deform_kernel<<<g2, 256>>>(out);
}